// round 9
// baseline (speedup 1.0000x reference)
#include <cuda_runtime.h>

#define NV 6
#define NT 3
#define NC 256
#define SP 1024
#define NHD 8
#define NB 144
#define SCALE 0.17677669529663687f
#define LN_EPS 1e-5f
#define NSLOT 8

// ---------------- scratch ----------------------------------------------------
__device__ float g_wqp[NC*NHD];         // paired: [(c/2)*16 + h*2 + (c&1)]
__device__ float g_S8[NSLOT*NHD*NC];    // slotted unnormalized sum_k e*kv, idx=h*256+c
__device__ float g_L8[NSLOT*NHD];
__device__ float g_u[NC];

__device__ __forceinline__ float wredsum(float v){
#pragma unroll
    for(int o=16;o;o>>=1) v += __shfl_down_sync(0xffffffffu, v, o);
    return v;
}
__device__ __forceinline__ unsigned long long packf2(float lo, float hi){
    unsigned long long r;
    asm("mov.b64 %0, {%1, %2};" : "=l"(r) : "f"(lo), "f"(hi));
    return r;
}
__device__ __forceinline__ float f2sum(unsigned long long a){
    float lo, hi;
    asm("mov.b64 {%0, %1}, %2;" : "=f"(lo), "=f"(hi) : "l"(a));
    return lo + hi;
}
#define FFMA2(acc, a, b) asm("fma.rn.f32x2 %0, %1, %2, %0;" : "+l"(acc) : "l"(a), "l"(b))

// ---------------- K0: per-head wq (paired layout) + zero accumulators --------
__global__ void k_prep(const float* __restrict__ qe, const float* __restrict__ cpe,
                       const float* __restrict__ spe, const float* __restrict__ qw,
                       const float* __restrict__ qb, const float* __restrict__ kw,
                       const int* __restrict__ qidx_p){
    int b = blockIdx.x, tid = threadIdx.x;
    if(b >= 8){
        int z = b - 8;
#pragma unroll
        for(int i=0;i<8;i++) g_S8[z*2048 + i*256 + tid] = 0.f;
        if(tid < NHD) g_L8[z*NHD + tid] = 0.f;
        return;
    }
    int h = b;
    __shared__ __align__(16) float qv[NC];
    __shared__ float qps[32];
    int qidx = qidx_p ? qidx_p[0] : 0;
    qv[tid] = qe[tid] + cpe[qidx*NC + tid] + spe[tid];
    __syncthreads();
    int w = tid >> 5, ln = tid & 31;
    const float4* qv4 = (const float4*)qv;
    float4 x = qv4[ln*2], y = qv4[ln*2+1];
#pragma unroll
    for(int k=0;k<4;k++){
        int j = h*32 + w*4 + k;
        const float4* qwr = (const float4*)(qw + (size_t)j*NC);
        float4 a = qwr[ln*2], b4 = qwr[ln*2+1];
        float d = a.x*x.x + a.y*x.y + a.z*x.z + a.w*x.w
                + b4.x*y.x + b4.y*y.y + b4.z*y.z + b4.w*y.w;
        d = wredsum(d);
        if(ln == 0) qps[w*4+k] = d + qb[j];
    }
    __syncthreads();
    float acc = 0.f;
    const float* kwb = kw + (size_t)(h*32)*NC + tid;
#pragma unroll
    for(int d=0; d<32; d++) acc += qps[d]*kwb[(size_t)d*NC];
    g_wqp[(tid>>1)*16 + h*2 + (tid&1)] = acc * SCALE;
}

// ---------------- K1: main pass — FUSED stage+score, then softmax+pass2 ------
__global__ __launch_bounds__(512,1)
void k_main(const float* __restrict__ hf, const float* __restrict__ tpe,
            const float* __restrict__ cpe){
    extern __shared__ float tile[];               // [256][130], 133120 B
    __shared__ float pe[NC];
    __shared__ __align__(16) float wq_sm[NC*NHD];       // paired layout
    __shared__ __align__(16) float p_sm[NHD*128];       // [h][pos]
    __shared__ float sred[4*NHD*128];                   // [q][h][pos]

    int tid = threadIdx.x;
    int b = blockIdx.x;
    int vt = b >> 3, chunk = b & 7;
    int v = vt / NT, t = vt - v*NT;
    int pos = tid & 127, q = tid >> 7;      // q: channel quarter 0..3
    int c0 = q*64;

    if(tid < 256) pe[tid] = tpe[t*NC + tid] + cpe[v*NC + tid];
#pragma unroll
    for(int k=0;k<4;k++) wq_sm[tid + k*512] = g_wqp[tid + k*512];
    __syncthreads();

    // -------- fused stage + score: compute score partials from registers -----
    // while the kv tile is staged; score FMAs hide under DRAM load latency.
    {
        const float* src = hf + ((size_t)(vt*NC + c0))*SP + chunk*128 + pos;
        unsigned long long acc2[8];
#pragma unroll
        for(int h=0;h<8;h++) acc2[h] = 0ULL;
        float r[16];
#pragma unroll
        for(int bch=0; bch<4; bch++){
#pragma unroll
            for(int j=0;j<16;j++) r[j] = src[(size_t)(bch*16+j)*SP];
#pragma unroll
            for(int j=0;j<16;j+=2){
                int c = c0 + bch*16 + j;
                float v0 = r[j]   + pe[c];
                float v1 = r[j+1] + pe[c+1];
                tile[c*130 + pos]     = v0;
                tile[(c+1)*130 + pos] = v1;
                unsigned long long kvp = packf2(v0, v1);
                const ulonglong2* wp = (const ulonglong2*)(wq_sm + (c>>1)*16);
                ulonglong2 w0 = wp[0], w1 = wp[1], w2 = wp[2], w3 = wp[3];
                FFMA2(acc2[0], kvp, w0.x); FFMA2(acc2[1], kvp, w0.y);
                FFMA2(acc2[2], kvp, w1.x); FFMA2(acc2[3], kvp, w1.y);
                FFMA2(acc2[4], kvp, w2.x); FFMA2(acc2[5], kvp, w2.y);
                FFMA2(acc2[6], kvp, w3.x); FFMA2(acc2[7], kvp, w3.y);
            }
        }
#pragma unroll
        for(int h=0;h<8;h++) sred[q*1024 + h*128 + pos] = f2sum(acc2[h]);
    }
    __syncthreads();

    // -------- scores -> e = exp(s) (|s| << 1, no max shift), local l ---------
    {
        int w = tid >> 5, ln = tid & 31;
        if(w < 8){
            float l = 0.f;
#pragma unroll
            for(int qq=0;qq<4;qq++){
                int p = ln + qq*32;
                float s = sred[w*128+p] + sred[1024+w*128+p]
                        + sred[2048+w*128+p] + sred[3072+w*128+p];
                float e = __expf(s);
                p_sm[w*128 + p] = e;
                l += e;
            }
            l = wredsum(l);
            if(ln == 0) atomicAdd(&g_L8[(b & (NSLOT-1))*NHD + w], l);
        }
    }
    __syncthreads();

    // -------- pass 2: partial[h][c] = sum_pos e*kv (f32x2 over pos-pairs) ----
    {
        int grp = tid >> 7, cid = tid & 127;      // 4 groups x 32 positions
        unsigned long long acc2[8][2];
#pragma unroll
        for(int h=0;h<8;h++){ acc2[h][0]=0ULL; acc2[h][1]=0ULL; }
        int p0 = grp*32;
#pragma unroll 2
        for(int pp=0;pp<16;pp++){
            int p = p0 + 2*pp;
            unsigned long long kv0 = *(const unsigned long long*)(tile + cid*130 + p);
            unsigned long long kv1 = *(const unsigned long long*)(tile + (cid+128)*130 + p);
#pragma unroll
            for(int h=0;h<8;h++){
                unsigned long long pv2 = *(const unsigned long long*)(p_sm + h*128 + p);
                FFMA2(acc2[h][0], pv2, kv0);
                FFMA2(acc2[h][1], pv2, kv1);
            }
        }
        __syncthreads();            // all tile reads done; reuse as staging
#pragma unroll
        for(int h=0;h<8;h++){
            tile[grp*2048 + h*256 + cid]       = f2sum(acc2[h][0]);
            tile[grp*2048 + h*256 + cid + 128] = f2sum(acc2[h][1]);
        }
    }
    __syncthreads();

    // -------- combine 4 groups, slotted atomic accumulate --------------------
    {
        int slot = b & (NSLOT-1);
#pragma unroll
        for(int k=0;k<4;k++){
            int idx = k*512 + tid;     // idx = h*256 + c
            float s = tile[idx] + tile[2048+idx] + tile[4096+idx] + tile[6144+idx];
            atomicAdd(&g_S8[slot*2048 + idx], s);
        }
    }
}

// ---------------- K2: fused t (redundant per block) + u (4 rows/block) -------
__global__ __launch_bounds__(512)
void k_tu(const float* __restrict__ vw, const float* __restrict__ vb,
          const float* __restrict__ ow, const float* __restrict__ ob){
    __shared__ __align__(16) float Sv[NHD*NC];   // 8KB, idx = h*256+c
    __shared__ float rL[NHD];
    __shared__ __align__(16) float t_sm[NC];
    __shared__ float red16[16];
    int b = blockIdx.x, tid = threadIdx.x;
    int w = tid >> 5, ln = tid & 31;

    if(tid < NHD){
        float L = 0.f;
#pragma unroll
        for(int r=0;r<NSLOT;r++) L += g_L8[r*NHD + tid];
        rL[tid] = 1.f / L;
    }
    __syncthreads();
#pragma unroll
    for(int k=0;k<4;k++){
        int idx = k*512 + tid;
        float s = 0.f;
#pragma unroll
        for(int r=0;r<NSLOT;r++) s += g_S8[r*2048 + idx];
        Sv[idx] = s * rL[idx >> 8];
    }
    __syncthreads();

    // ---- t[256]: 16 warps x 16 rows each, warp-per-row coalesced GEMV -------
#pragma unroll
    for(int it=0; it<16; it++){
        int row = w*16 + it;
        const float4* vr = (const float4*)(vw + (size_t)row*NC);
        const float4* sv = (const float4*)(Sv + (row>>5)*256);
        float4 a = vr[ln*2], b4 = vr[ln*2+1];
        float4 x = sv[ln*2], y = sv[ln*2+1];
        float d = a.x*x.x + a.y*x.y + a.z*x.z + a.w*x.w
                + b4.x*y.x + b4.y*y.y + b4.z*y.z + b4.w*y.w;
        d = wredsum(d);
        if(ln == 0) t_sm[row] = d + vb[row];
    }
    __syncthreads();

    // ---- u rows for this block: j = b*4 + r, 128 threads per row ------------
    {
        int r = tid >> 7, cid = tid & 127;
        int j = b*4 + r;
        float2 o2 = ((const float2*)(ow + (size_t)j*NC))[cid];
        float2 t2 = ((const float2*)t_sm)[cid];
        float part = o2.x*t2.x + o2.y*t2.y;
        part = wredsum(part);
        if(ln == 0) red16[w] = part;
        __syncthreads();
        if(tid < 4){
            float s = red16[tid*4] + red16[tid*4+1] + red16[tid*4+2] + red16[tid*4+3];
            g_u[b*4 + tid] = s + ob[b*4 + tid];
        }
    }
}

// ---------------- K3: fused LayerNorm + broadcast (proven) -------------------
__global__ void k_bcast(const float* __restrict__ lng, const float* __restrict__ lnb,
                        float* __restrict__ out){
    __shared__ float r1[8], r2[8];
    int tid = threadIdx.x, c = blockIdx.x;
    float uv = g_u[tid];
    float s1 = wredsum(uv);
    float s2 = wredsum(uv*uv);
    int w = tid >> 5, ln = tid & 31;
    if(ln == 0){ r1[w] = s1; r2[w] = s2; }
    __syncthreads();
    if(w == 0){
        float a = (ln < 8) ? r1[ln] : 0.f;
        float b = (ln < 8) ? r2[ln] : 0.f;
#pragma unroll
        for(int o=4;o;o>>=1){ a += __shfl_down_sync(0xffffffffu,a,o); b += __shfl_down_sync(0xffffffffu,b,o); }
        if(ln == 0){ r1[0] = a; r2[0] = b; }
    }
    __syncthreads();
    float mu  = r1[0] * (1.f/NC);
    float var = r2[0] * (1.f/NC) - mu*mu;
    float yv = (g_u[c] - mu) * rsqrtf(var + LN_EPS) * lng[c] + lnb[c];
    float4 v = make_float4(yv, yv, yv, yv);
    ((float4*)out)[c*256 + tid] = v;
}

// ---------------- launch -----------------------------------------------------
extern "C" void kernel_launch(void* const* d_in, const int* in_sizes, int n_in,
                              void* d_out, int out_size){
    const float* hf  = (const float*)d_in[0];
    const float* qe  = (const float*)d_in[1];
    const float* cpe = (const float*)d_in[2];
    const float* tpe = (const float*)d_in[3];
    const float* spe = (const float*)d_in[4];
    const float* qw  = (const float*)d_in[5];
    const float* qb  = (const float*)d_in[6];
    const float* kw  = (const float*)d_in[7];
    // d_in[8] = k_b: cancels in softmax (constant per-head shift)
    const float* vw  = (const float*)d_in[9];
    const float* vb  = (const float*)d_in[10];
    const float* ow  = (const float*)d_in[11];
    const float* ob  = (const float*)d_in[12];
    const float* lng = (const float*)d_in[13];
    const float* lnb = (const float*)d_in[14];
    const int*  qidx = (n_in > 15) ? (const int*)d_in[15] : nullptr;

    const int main_smem = 256*130*4;               // 133120
    cudaFuncSetAttribute(k_main, cudaFuncAttributeMaxDynamicSharedMemorySize, main_smem);

    k_prep <<<16, 256>>>(qe, cpe, spe, qw, qb, kw, qidx);
    k_main <<<NB, 512, main_smem>>>(hf, tpe, cpe);
    k_tu   <<<64, 512>>>(vw, vb, ow, ob);
    k_bcast<<<256, 256>>>(lng, lnb, (float*)d_out);
}

// round 11
// speedup vs baseline: 1.1913x; 1.1913x over previous
#include <cuda_runtime.h>

#define NV 6
#define NT 3
#define NC 256
#define SP 1024
#define NHD 8
#define CHUNK 128
#define NB 144
#define SCALE 0.17677669529663687f
#define LN_EPS 1e-5f
#define NSLOT 8

// ---------------- scratch (zero-initialized at module load) ------------------
__device__ float g_wq[NC*NHD];          // [c*8+h]
__device__ float g_S8[NSLOT*NHD*NC];    // slotted unnormalized sum_k e*kv
__device__ float g_L8[NSLOT*NHD];       // slotted sum_k e
__device__ float g_t[NC];
__device__ float g_u[NC];
__device__ unsigned int g_flag;         // wq-ready flag; reset by k_bcast

__device__ __forceinline__ float wredsum(float v){
#pragma unroll
    for(int o=16;o;o>>=1) v += __shfl_down_sync(0xffffffffu, v, o);
    return v;
}

// ---------------- K1: main pass with inlined prep (blocks 0..7) --------------
__global__ __launch_bounds__(512,1)
void k_main(const float* __restrict__ hf,  const float* __restrict__ tpe,
            const float* __restrict__ cpe, const float* __restrict__ qe,
            const float* __restrict__ spe, const float* __restrict__ qw,
            const float* __restrict__ qb,  const float* __restrict__ kw,
            const int*   __restrict__ qidx_p){
    extern __shared__ float tile[];               // [256][129], 132096 B
    __shared__ float pe[NC];
    __shared__ __align__(16) float wq_sm[NC*NHD];
    __shared__ __align__(16) float p_sm[CHUNK*NHD];     // [pos*8+h]
    __shared__ __align__(16) float sred[4*NHD*CHUNK];   // [q][h][pos]; also prep scratch

    int tid = threadIdx.x;
    int b = blockIdx.x;
    int vt = b >> 3, chunk = b & 7;
    int v = vt / NT, t = vt - v*NT;
    int pos = tid & 127, q = tid >> 7;      // q: channel quarter 0..3
    int c0 = q*64;
    int w = tid >> 5, ln = tid & 31;

    if(tid < 256) pe[tid] = tpe[t*NC + tid] + cpe[v*NC + tid];
    __syncthreads();    // pe visible to ALL threads before staging (R10 bugfix)

    // -------- inlined prep: blocks 0..7 compute head-b wq, publish flag ------
    if(b < 8){
        int h = b;
        if(tid < 256){
            int qidx = qidx_p ? qidx_p[0] : 0;
            sred[tid] = qe[tid] + cpe[qidx*NC + tid] + spe[tid];   // qv
        }
        __syncthreads();
        if(w < 8){
            const float4* qv4 = (const float4*)sred;
            float4 x = qv4[ln*2], y = qv4[ln*2+1];
#pragma unroll
            for(int k=0;k<4;k++){
                int j = h*32 + w*4 + k;
                const float4* qwr = (const float4*)(qw + (size_t)j*NC);
                float4 a = qwr[ln*2], b4 = qwr[ln*2+1];
                float d = a.x*x.x + a.y*x.y + a.z*x.z + a.w*x.w
                        + b4.x*y.x + b4.y*y.y + b4.z*y.z + b4.w*y.w;
                d = wredsum(d);
                if(ln == 0) sred[256 + w*4 + k] = d + qb[j];       // qp[32]
            }
        }
        __syncthreads();
        if(tid < 256){
            float acc = 0.f;
            const float* kwb = kw + (size_t)(h*32)*NC + tid;
#pragma unroll
            for(int d=0; d<32; d++) acc += sred[256 + d]*kwb[(size_t)d*NC];
            g_wq[tid*NHD + h] = acc * SCALE;
        }
        __syncthreads();
        __threadfence();
        if(tid == 0) atomicAdd(&g_flag, 1u);
        __syncthreads();
    }

    // -------- stage kv tile: 64 channels/thread, 16 loads in flight ----------
    {
        const float* src = hf + ((size_t)(vt*NC + c0))*SP + chunk*CHUNK + pos;
        float r[16];
#pragma unroll
        for(int bch=0; bch<4; bch++){
#pragma unroll
            for(int j=0;j<16;j++) r[j] = src[(size_t)(bch*16+j)*SP];
#pragma unroll
            for(int j=0;j<16;j++){
                int c = c0 + bch*16 + j;
                tile[c*129 + pos] = r[j] + pe[c];
            }
        }
    }
    __syncthreads();

    // -------- wait for all 8 wq heads, then load wq into smem ----------------
    if(tid == 0){
        unsigned int fv;
        for(;;){
            asm volatile("ld.acquire.gpu.global.u32 %0, [%1];" : "=r"(fv) : "l"(&g_flag));
            if(fv >= 8u) break;
            __nanosleep(32);
        }
    }
    __syncthreads();
#pragma unroll
    for(int k=0;k<4;k++) wq_sm[tid + k*512] = __ldcg(&g_wq[tid + k*512]);
    __syncthreads();

    // -------- pass 1: per-quarter score partials -----------------------------
    {
        float acc[8];
#pragma unroll
        for(int h=0;h<8;h++) acc[h]=0.f;
        const float4* wq4 = (const float4*)wq_sm;
#pragma unroll 4
        for(int i=0;i<64;i++){
            int c = c0 + i;
            float kv = tile[c*129 + pos];
            float4 w0 = wq4[c*2], w1 = wq4[c*2+1];
            acc[0] += kv*w0.x; acc[1] += kv*w0.y; acc[2] += kv*w0.z; acc[3] += kv*w0.w;
            acc[4] += kv*w1.x; acc[5] += kv*w1.y; acc[6] += kv*w1.z; acc[7] += kv*w1.w;
        }
#pragma unroll
        for(int h=0;h<8;h++) sred[q*1024 + h*128 + pos] = acc[h];
    }
    __syncthreads();

    // -------- scores -> e = exp(s) (|s| << 1, no max shift), local l ---------
    {
        if(w < 8){
            float l = 0.f;
#pragma unroll
            for(int qq=0;qq<4;qq++){
                int p = ln + qq*32;
                float s = sred[w*128+p] + sred[1024+w*128+p]
                        + sred[2048+w*128+p] + sred[3072+w*128+p];
                float e = __expf(s);
                p_sm[p*8 + w] = e;
                l += e;
            }
            l = wredsum(l);
            if(ln == 0) atomicAdd(&g_L8[(b & (NSLOT-1))*NHD + w], l);
        }
    }
    __syncthreads();

    // -------- pass 2: partial[h][c] = sum_pos e*kv ---------------------------
    {
        int grp = tid >> 6, cid = tid & 63;       // 8 groups x 16 positions
        float acc[8][4];
#pragma unroll
        for(int h=0;h<8;h++)
#pragma unroll
            for(int qq=0;qq<4;qq++) acc[h][qq]=0.f;
        const float4* p4 = (const float4*)p_sm;
        int p0 = grp*16;
#pragma unroll 2
        for(int pp=0;pp<16;pp++){
            int p = p0 + pp;
            float4 pa = p4[p*2], pb = p4[p*2+1];
            float pv[8] = {pa.x,pa.y,pa.z,pa.w,pb.x,pb.y,pb.z,pb.w};
            float kvv[4];
#pragma unroll
            for(int qq=0;qq<4;qq++) kvv[qq] = tile[(cid + qq*64)*129 + p];
#pragma unroll
            for(int h=0;h<8;h++)
#pragma unroll
                for(int qq=0;qq<4;qq++) acc[h][qq] += pv[h]*kvv[qq];
        }
        __syncthreads();            // all tile reads done; reuse as staging
#pragma unroll
        for(int h=0;h<8;h++)
#pragma unroll
            for(int qq=0;qq<4;qq++)
                tile[grp*2048 + h*256 + (cid + qq*64)] = acc[h][qq];
    }
    __syncthreads();

    // -------- combine 8 groups, slotted atomic accumulate --------------------
    {
        int slot = b & (NSLOT-1);
#pragma unroll
        for(int k=0;k<4;k++){
            int idx = k*512 + tid;     // idx = h*256 + c
            float s = 0.f;
#pragma unroll
            for(int g=0; g<8; g++) s += tile[g*2048 + idx];
            atomicAdd(&g_S8[slot*2048 + idx], s);
        }
    }
}

// ---------------- K2: slot-reduce + normalize + V-GEMV (R4 proven) -----------
__global__ void k_t(const float* __restrict__ vw, const float* __restrict__ vb){
    __shared__ __align__(16) float S_sm[NC];
    int b = blockIdx.x, tid = threadIdx.x;
    int h = b >> 2;                                // 4 blocks per head
    float s = 0.f;
#pragma unroll
    for(int r=0;r<NSLOT;r++) s += g_S8[r*2048 + h*256 + tid];
    float L = 0.f;
#pragma unroll
    for(int r=0;r<NSLOT;r++) L += g_L8[r*NHD + h];
    S_sm[tid] = s / L;
    __syncthreads();

    int w = tid >> 5, ln = tid & 31;
    int j = b*8 + w;                                // 8 warps -> 8 rows
    const float4* S4 = (const float4*)S_sm;
    float4 x = S4[ln*2], y = S4[ln*2+1];
    const float4* vr = (const float4*)(vw + (size_t)j*NC);
    float4 a = vr[ln*2], b4 = vr[ln*2+1];
    float d = a.x*x.x + a.y*x.y + a.z*x.z + a.w*x.w
            + b4.x*y.x + b4.y*y.y + b4.z*y.z + b4.w*y.w;
    d = wredsum(d);
    if(ln == 0) g_t[j] = d + vb[j];
}

// ---------------- K3: O-projection GEMV (R4 proven) --------------------------
__global__ void k_u(const float* __restrict__ ow, const float* __restrict__ ob){
    __shared__ __align__(16) float t_sm[NC];
    int b = blockIdx.x, tid = threadIdx.x;
    t_sm[tid] = g_t[tid];
    __syncthreads();
    int w = tid >> 5, ln = tid & 31;
    int c = b*8 + w;
    const float4* t4 = (const float4*)t_sm;
    float4 x = t4[ln*2], y = t4[ln*2+1];
    const float4* orow = (const float4*)(ow + (size_t)c*NC);
    float4 a = orow[ln*2], b4 = orow[ln*2+1];
    float d = a.x*x.x + a.y*x.y + a.z*x.z + a.w*x.w
            + b4.x*y.x + b4.y*y.y + b4.z*y.z + b4.w*y.w;
    d = wredsum(d);
    if(ln == 0) g_u[c] = d + ob[c];
}

// ---------------- K4: LayerNorm + broadcast + state reset --------------------
__global__ void k_bcast(const float* __restrict__ lng, const float* __restrict__ lnb,
                        float* __restrict__ out){
    __shared__ float r1[8], r2[8];
    int tid = threadIdx.x, c = blockIdx.x;
    float uv = g_u[tid];
    float s1 = wredsum(uv);
    float s2 = wredsum(uv*uv);
    int w = tid >> 5, ln = tid & 31;
    if(ln == 0){ r1[w] = s1; r2[w] = s2; }
    __syncthreads();
    if(w == 0){
        float a = (ln < 8) ? r1[ln] : 0.f;
        float b = (ln < 8) ? r2[ln] : 0.f;
#pragma unroll
        for(int o=4;o;o>>=1){ a += __shfl_down_sync(0xffffffffu,a,o); b += __shfl_down_sync(0xffffffffu,b,o); }
        if(ln == 0){ r1[0] = a; r2[0] = b; }
    }
    __syncthreads();
    float mu  = r1[0] * (1.f/NC);
    float var = r2[0] * (1.f/NC) - mu*mu;
    float yv = (g_u[c] - mu) * rsqrtf(var + LN_EPS) * lng[c] + lnb[c];
    float4 v = make_float4(yv, yv, yv, yv);
    ((float4*)out)[c*256 + tid] = v;

    // ---- reset accumulators/flag for the next launch (consumers are done) ---
    if(tid < 64) g_S8[c*64 + tid] = 0.f;           // 256 blocks x 64 = 16384
    if(c == 0 && tid < NSLOT*NHD) g_L8[tid] = 0.f;
    if(c == 0 && tid == 0) g_flag = 0u;
}

// ---------------- launch -----------------------------------------------------
extern "C" void kernel_launch(void* const* d_in, const int* in_sizes, int n_in,
                              void* d_out, int out_size){
    const float* hf  = (const float*)d_in[0];
    const float* qe  = (const float*)d_in[1];
    const float* cpe = (const float*)d_in[2];
    const float* tpe = (const float*)d_in[3];
    const float* spe = (const float*)d_in[4];
    const float* qw  = (const float*)d_in[5];
    const float* qb  = (const float*)d_in[6];
    const float* kw  = (const float*)d_in[7];
    // d_in[8] = k_b: cancels in softmax (constant per-head shift)
    const float* vw  = (const float*)d_in[9];
    const float* vb  = (const float*)d_in[10];
    const float* ow  = (const float*)d_in[11];
    const float* ob  = (const float*)d_in[12];
    const float* lng = (const float*)d_in[13];
    const float* lnb = (const float*)d_in[14];
    const int*  qidx = (n_in > 15) ? (const int*)d_in[15] : nullptr;

    const int smem_bytes = 256*129*4;   // 132096 -> 1 CTA/SM -> co-residency
    cudaFuncSetAttribute(k_main, cudaFuncAttributeMaxDynamicSharedMemorySize, smem_bytes);

    k_main <<<NB, 512, smem_bytes>>>(hf, tpe, cpe, qe, spe, qw, qb, kw, qidx);
    k_t    <<<32, 256>>>(vw, vb);
    k_u    <<<32, 256>>>(ow, ob);
    k_bcast<<<256, 256>>>(lng, lnb, (float*)d_out);
}

// round 12
// speedup vs baseline: 1.2058x; 1.0122x over previous
#include <cuda_runtime.h>

#define NV 6
#define NT 3
#define NC 256
#define SP 1024
#define NHD 8
#define CHUNK 128
#define NB 144
#define SCALE 0.17677669529663687f
#define LN_EPS 1e-5f
#define NSLOT 8

// ---------------- scratch (zero-initialized at module load) ------------------
__device__ float g_wq[NC*NHD];          // [c*8+h]
__device__ float g_S8[NSLOT*NHD*NC];    // slotted unnormalized sum_k e*kv
__device__ float g_L8[NSLOT*NHD];       // slotted sum_k e
__device__ float g_t[NC];
__device__ float g_u[NC];
__device__ float g_stat[2];             // [sum u, sum u^2]
__device__ unsigned int g_flag;         // wq-ready flag
__device__ unsigned int g_cnt;          // t-ready counter

__device__ __forceinline__ float wredsum(float v){
#pragma unroll
    for(int o=16;o;o>>=1) v += __shfl_down_sync(0xffffffffu, v, o);
    return v;
}
__device__ __forceinline__ void spin_until(unsigned int* p, unsigned int target){
    unsigned int fv;
    for(;;){
        asm volatile("ld.acquire.gpu.global.u32 %0, [%1];" : "=r"(fv) : "l"(p));
        if(fv >= target) break;
        __nanosleep(32);
    }
}

// ---------------- K1: main pass with inlined prep (R11 proven) ---------------
__global__ __launch_bounds__(512,1)
void k_main(const float* __restrict__ hf,  const float* __restrict__ tpe,
            const float* __restrict__ cpe, const float* __restrict__ qe,
            const float* __restrict__ spe, const float* __restrict__ qw,
            const float* __restrict__ qb,  const float* __restrict__ kw,
            const int*   __restrict__ qidx_p){
    extern __shared__ float tile[];               // [256][129], 132096 B
    __shared__ float pe[NC];
    __shared__ __align__(16) float wq_sm[NC*NHD];
    __shared__ __align__(16) float p_sm[CHUNK*NHD];     // [pos*8+h]
    __shared__ __align__(16) float sred[4*NHD*CHUNK];   // [q][h][pos]; also prep scratch

    int tid = threadIdx.x;
    int b = blockIdx.x;
    int vt = b >> 3, chunk = b & 7;
    int v = vt / NT, t = vt - v*NT;
    int pos = tid & 127, q = tid >> 7;      // q: channel quarter 0..3
    int c0 = q*64;
    int w = tid >> 5, ln = tid & 31;

    if(tid < 256) pe[tid] = tpe[t*NC + tid] + cpe[v*NC + tid];
    __syncthreads();    // pe visible to ALL threads before staging

    // -------- inlined prep: blocks 0..7 compute head-b wq, publish flag ------
    if(b < 8){
        int h = b;
        if(tid < 256){
            int qidx = qidx_p ? qidx_p[0] : 0;
            sred[tid] = qe[tid] + cpe[qidx*NC + tid] + spe[tid];   // qv
        }
        __syncthreads();
        if(w < 8){
            const float4* qv4 = (const float4*)sred;
            float4 x = qv4[ln*2], y = qv4[ln*2+1];
#pragma unroll
            for(int k=0;k<4;k++){
                int j = h*32 + w*4 + k;
                const float4* qwr = (const float4*)(qw + (size_t)j*NC);
                float4 a = qwr[ln*2], b4 = qwr[ln*2+1];
                float d = a.x*x.x + a.y*x.y + a.z*x.z + a.w*x.w
                        + b4.x*y.x + b4.y*y.y + b4.z*y.z + b4.w*y.w;
                d = wredsum(d);
                if(ln == 0) sred[256 + w*4 + k] = d + qb[j];       // qp[32]
            }
        }
        __syncthreads();
        if(tid < 256){
            float acc = 0.f;
            const float* kwb = kw + (size_t)(h*32)*NC + tid;
#pragma unroll
            for(int d=0; d<32; d++) acc += sred[256 + d]*kwb[(size_t)d*NC];
            g_wq[tid*NHD + h] = acc * SCALE;
        }
        __syncthreads();
        __threadfence();
        if(tid == 0) atomicAdd(&g_flag, 1u);
        __syncthreads();
    }

    // -------- stage kv tile: 64 channels/thread, 16 loads in flight ----------
    {
        const float* src = hf + ((size_t)(vt*NC + c0))*SP + chunk*CHUNK + pos;
        float r[16];
#pragma unroll
        for(int bch=0; bch<4; bch++){
#pragma unroll
            for(int j=0;j<16;j++) r[j] = src[(size_t)(bch*16+j)*SP];
#pragma unroll
            for(int j=0;j<16;j++){
                int c = c0 + bch*16 + j;
                tile[c*129 + pos] = r[j] + pe[c];
            }
        }
    }
    __syncthreads();

    // -------- wait for all 8 wq heads, then load wq into smem ----------------
    if(tid == 0) spin_until(&g_flag, 8u);
    __syncthreads();
#pragma unroll
    for(int k=0;k<4;k++) wq_sm[tid + k*512] = __ldcg(&g_wq[tid + k*512]);
    __syncthreads();

    // -------- pass 1: per-quarter score partials -----------------------------
    {
        float acc[8];
#pragma unroll
        for(int h=0;h<8;h++) acc[h]=0.f;
        const float4* wq4 = (const float4*)wq_sm;
#pragma unroll 4
        for(int i=0;i<64;i++){
            int c = c0 + i;
            float kv = tile[c*129 + pos];
            float4 w0 = wq4[c*2], w1 = wq4[c*2+1];
            acc[0] += kv*w0.x; acc[1] += kv*w0.y; acc[2] += kv*w0.z; acc[3] += kv*w0.w;
            acc[4] += kv*w1.x; acc[5] += kv*w1.y; acc[6] += kv*w1.z; acc[7] += kv*w1.w;
        }
#pragma unroll
        for(int h=0;h<8;h++) sred[q*1024 + h*128 + pos] = acc[h];
    }
    __syncthreads();

    // -------- scores -> e = exp(s) (|s| << 1, no max shift), local l ---------
    {
        if(w < 8){
            float l = 0.f;
#pragma unroll
            for(int qq=0;qq<4;qq++){
                int p = ln + qq*32;
                float s = sred[w*128+p] + sred[1024+w*128+p]
                        + sred[2048+w*128+p] + sred[3072+w*128+p];
                float e = __expf(s);
                p_sm[p*8 + w] = e;
                l += e;
            }
            l = wredsum(l);
            if(ln == 0) atomicAdd(&g_L8[(b & (NSLOT-1))*NHD + w], l);
        }
    }
    __syncthreads();

    // -------- pass 2: partial[h][c] = sum_pos e*kv ---------------------------
    {
        int grp = tid >> 6, cid = tid & 63;       // 8 groups x 16 positions
        float acc[8][4];
#pragma unroll
        for(int h=0;h<8;h++)
#pragma unroll
            for(int qq=0;qq<4;qq++) acc[h][qq]=0.f;
        const float4* p4 = (const float4*)p_sm;
        int p0 = grp*16;
#pragma unroll 2
        for(int pp=0;pp<16;pp++){
            int p = p0 + pp;
            float4 pa = p4[p*2], pb = p4[p*2+1];
            float pv[8] = {pa.x,pa.y,pa.z,pa.w,pb.x,pb.y,pb.z,pb.w};
            float kvv[4];
#pragma unroll
            for(int qq=0;qq<4;qq++) kvv[qq] = tile[(cid + qq*64)*129 + p];
#pragma unroll
            for(int h=0;h<8;h++)
#pragma unroll
                for(int qq=0;qq<4;qq++) acc[h][qq] += pv[h]*kvv[qq];
        }
        __syncthreads();            // all tile reads done; reuse as staging
#pragma unroll
        for(int h=0;h<8;h++)
#pragma unroll
            for(int qq=0;qq<4;qq++)
                tile[grp*2048 + h*256 + (cid + qq*64)] = acc[h][qq];
    }
    __syncthreads();

    // -------- combine 8 groups, slotted atomic accumulate --------------------
    {
        int slot = b & (NSLOT-1);
#pragma unroll
        for(int k=0;k<4;k++){
            int idx = k*512 + tid;     // idx = h*256 + c
            float s = 0.f;
#pragma unroll
            for(int g=0; g<8; g++) s += tile[g*2048 + idx];
            atomicAdd(&g_S8[slot*2048 + idx], s);
        }
    }
}

// ---------------- K2: fused t-GEMV -> flag -> u-GEMV + LN stats --------------
__global__ void k_tu(const float* __restrict__ vw, const float* __restrict__ vb,
                     const float* __restrict__ ow, const float* __restrict__ ob){
    __shared__ __align__(16) float S_sm[NC];
    __shared__ float u8[8];
    int b = blockIdx.x, tid = threadIdx.x;
    int w = tid >> 5, ln = tid & 31;

    // ---- t phase (R4-proven body): block b -> rows b*8 .. b*8+7 -------------
    {
        int h = b >> 2;                            // 4 blocks per head
        float s = 0.f;
#pragma unroll
        for(int r=0;r<NSLOT;r++) s += g_S8[r*2048 + h*256 + tid];
        float L = 0.f;
#pragma unroll
        for(int r=0;r<NSLOT;r++) L += g_L8[r*NHD + h];
        S_sm[tid] = s / L;
    }
    __syncthreads();
    {
        int j = b*8 + w;                           // 8 warps -> 8 rows
        const float4* S4 = (const float4*)S_sm;
        float4 x = S4[ln*2], y = S4[ln*2+1];
        const float4* vr = (const float4*)(vw + (size_t)j*NC);
        float4 a = vr[ln*2], b4 = vr[ln*2+1];
        float d = a.x*x.x + a.y*x.y + a.z*x.z + a.w*x.w
                + b4.x*y.x + b4.y*y.y + b4.z*y.z + b4.w*y.w;
        d = wredsum(d);
        if(ln == 0) g_t[j] = d + vb[j];
    }
    __syncthreads();
    __threadfence();
    if(tid == 0) atomicAdd(&g_cnt, 1u);

    // ---- wait for full t, load into smem ------------------------------------
    if(tid == 0) spin_until(&g_cnt, 32u);
    __syncthreads();
    S_sm[tid] = __ldcg(&g_t[tid]);
    __syncthreads();

    // ---- u phase (R4-proven body) + LN partial stats ------------------------
    {
        int c = b*8 + w;
        const float4* t4 = (const float4*)S_sm;
        float4 x = t4[ln*2], y = t4[ln*2+1];
        const float4* orow = (const float4*)(ow + (size_t)c*NC);
        float4 a = orow[ln*2], b4 = orow[ln*2+1];
        float d = a.x*x.x + a.y*x.y + a.z*x.z + a.w*x.w
                + b4.x*y.x + b4.y*y.y + b4.z*y.z + b4.w*y.w;
        d = wredsum(d);
        if(ln == 0){
            float uv = d + ob[c];
            g_u[c] = uv;
            u8[w] = uv;
        }
    }
    __syncthreads();
    if(tid == 0){
        float s1 = 0.f, s2 = 0.f;
#pragma unroll
        for(int k=0;k<8;k++){ float uv = u8[k]; s1 += uv; s2 += uv*uv; }
        atomicAdd(&g_stat[0], s1);
        atomicAdd(&g_stat[1], s2);
    }
}

// ---------------- K3: LayerNorm apply + broadcast + state reset --------------
__global__ void k_bcast(const float* __restrict__ lng, const float* __restrict__ lnb,
                        float* __restrict__ out){
    int tid = threadIdx.x, c = blockIdx.x;
    float mu  = g_stat[0] * (1.f/NC);
    float var = g_stat[1] * (1.f/NC) - mu*mu;
    float yv = (g_u[c] - mu) * rsqrtf(var + LN_EPS) * lng[c] + lnb[c];
    float4 v = make_float4(yv, yv, yv, yv);
    ((float4*)out)[c*256 + tid] = v;

    // ---- reset accumulators/flags for the next launch (consumers done) ------
    if(tid < 64) g_S8[c*64 + tid] = 0.f;           // 256 blocks x 64 = 16384
    if(c == 0){
        if(tid < NSLOT*NHD) g_L8[tid] = 0.f;
        if(tid == 64){ g_flag = 0u; g_cnt = 0u; g_stat[0] = 0.f; g_stat[1] = 0.f; }
    }
}

// ---------------- launch -----------------------------------------------------
extern "C" void kernel_launch(void* const* d_in, const int* in_sizes, int n_in,
                              void* d_out, int out_size){
    const float* hf  = (const float*)d_in[0];
    const float* qe  = (const float*)d_in[1];
    const float* cpe = (const float*)d_in[2];
    const float* tpe = (const float*)d_in[3];
    const float* spe = (const float*)d_in[4];
    const float* qw  = (const float*)d_in[5];
    const float* qb  = (const float*)d_in[6];
    const float* kw  = (const float*)d_in[7];
    // d_in[8] = k_b: cancels in softmax (constant per-head shift)
    const float* vw  = (const float*)d_in[9];
    const float* vb  = (const float*)d_in[10];
    const float* ow  = (const float*)d_in[11];
    const float* ob  = (const float*)d_in[12];
    const float* lng = (const float*)d_in[13];
    const float* lnb = (const float*)d_in[14];
    const int*  qidx = (n_in > 15) ? (const int*)d_in[15] : nullptr;

    const int smem_bytes = 256*129*4;   // 132096 -> 1 CTA/SM -> co-residency
    cudaFuncSetAttribute(k_main, cudaFuncAttributeMaxDynamicSharedMemorySize, smem_bytes);

    k_main <<<NB, 512, smem_bytes>>>(hf, tpe, cpe, qe, spe, qw, qb, kw, qidx);
    k_tu   <<<32, 256>>>(vw, vb, ow, ob);
    k_bcast<<<256, 256>>>(lng, lnb, (float*)d_out);
}